// round 17
// baseline (speedup 1.0000x reference)
#include <cuda_runtime.h>
#include <cstdint>

// ---------------------------------------------------------------------------
// x      : [4, 2048, 4096] fp32  -> M = 8192, K = 4096
// weight : [4096, 4096]    fp32  -> N = 4096 (row-major [N, K], K contiguous)
// bias   : [4096]          fp32
// out    : [8192, 4096]    fp32
//
// Quantize to int8 values carried as bf16; GEMM on legacy bf16 HMMA
// (m16n8k16, f32 accum) — bit-exact vs the int32 MAC for this value range.
// ---------------------------------------------------------------------------
#define M_DIM 8192
#define N_DIM 4096
#define K_DIM 4096

#define BM 128
#define BN 128
#define BK 64                          // 64 bf16 = 128B per row
#define NS 3
#define NIT (K_DIM / BK)               // 64
#define A_STAGE (BM * 128)             // 16384 bytes
#define B_STAGE (BN * 128)             // 16384 bytes
#define B_OFF (NS * A_STAGE)           // 49152
#define SMEM_TC (NS * (A_STAGE + B_STAGE))  // 98304 -> 2 CTAs/SM
#define STAGE_BYTES_TX (A_STAGE + B_STAGE)  // 32768

// Scratch: pre-swizzled tile-major bf16 (allocation-free rule).
// A: [mb=64][kb=64][row=128][128B swizzled]  = 64 MB
// B: [nb=32][kb=64][row=128][128B swizzled]  = 32 MB
__device__ __align__(256) unsigned short g_qxb[(size_t)M_DIM * K_DIM];
__device__ __align__(256) unsigned short g_qwb[(size_t)N_DIM * K_DIM];
__device__ unsigned g_amax[2];

// ---------------------------------------------------------------------------
__global__ void hx_init() {
    g_amax[0] = 0u;
    g_amax[1] = 0u;
}

// Merged amax: blocks [0,2048) reduce x, [2048,3072) reduce w.
// Bit-pattern max over |v| is exact for non-negative IEEE floats.
__global__ void hx_amax2(const float4* __restrict__ x,
                         const float4* __restrict__ w) {
    const int which = (blockIdx.x >= 2048) ? 1 : 0;
    const float4* __restrict__ src = which ? w : x;
    const int n4 = which ? (N_DIM * K_DIM / 4) : (M_DIM * K_DIM / 4);
    const int nblk = which ? 1024 : 2048;
    const int bid = which ? (blockIdx.x - 2048) : blockIdx.x;

    unsigned m = 0u;
    const int stride = nblk * blockDim.x;
    for (int i = bid * blockDim.x + threadIdx.x; i < n4; i += stride) {
        float4 v = src[i];
        m = max(m, __float_as_uint(fabsf(v.x)));
        m = max(m, __float_as_uint(fabsf(v.y)));
        m = max(m, __float_as_uint(fabsf(v.z)));
        m = max(m, __float_as_uint(fabsf(v.w)));
    }
#pragma unroll
    for (int o = 16; o > 0; o >>= 1)
        m = max(m, __shfl_xor_sync(0xffffffffu, m, o));
    __shared__ unsigned red[8];
    if ((threadIdx.x & 31) == 0) red[threadIdx.x >> 5] = m;
    __syncthreads();
    if (threadIdx.x == 0) {
        unsigned v = red[0];
#pragma unroll
        for (int i = 1; i < 8; ++i) v = max(v, red[i]);
        atomicMax(&g_amax[which], v);
    }
}

// ---------------------------------------------------------------------------
// Quantize to integer-valued bf16, pre-swizzled tile-major.
// q = clip(rint(v * 127/amax), -127, 127); rintf == jnp.round (half-even).
// ---------------------------------------------------------------------------
__device__ __forceinline__ float qval(float v, float s) {
    return fminf(127.f, fmaxf(-127.f, rintf(v * s)));
}
__device__ __forceinline__ uint32_t bf2(float lo, float hi) {
    uint32_t r;
    asm("cvt.rn.bf16x2.f32 %0, %1, %2;" : "=r"(r) : "f"(hi), "f"(lo));
    return r;
}
__device__ __forceinline__ uint4 pack8(float4 a, float4 b, float s) {
    uint4 q;
    q.x = bf2(qval(a.x, s), qval(a.y, s));
    q.y = bf2(qval(a.z, s), qval(a.w, s));
    q.z = bf2(qval(b.x, s), qval(b.y, s));
    q.w = bf2(qval(b.z, s), qval(b.w, s));
    return q;
}

// Merged quant: blocks [0,16384) -> A; [16384,24576) -> B.
// thread = (row r, 16B out-chunk cc of 512); 128-row blocks both sides.
__global__ void hx_quant2(const float4* __restrict__ x,
                          const float4* __restrict__ w) {
    const int isB = (blockIdx.x >= 16384) ? 1 : 0;
    const int bid = isB ? (blockIdx.x - 16384) : blockIdx.x;
    const int tid = bid * blockDim.x + threadIdx.x;
    const int r = tid >> 9, cc = tid & 511;
    const float s = 127.0f / __uint_as_float(g_amax[isB]);
    const float4* __restrict__ src = isB ? w : x;
    const float4* p = src + (size_t)r * 1024 + cc * 2;
    const uint4 q = pack8(p[0], p[1], s);
    const int blk = r >> 7, row = r & 127, kb = cc >> 3, c = cc & 7;
    const size_t off =
        ((size_t)((blk * 64 + kb) * 128 + row)) * 128 + ((c ^ (row & 7)) << 4);
    char* dst = isB ? reinterpret_cast<char*>(g_qwb) : reinterpret_cast<char*>(g_qxb);
    *reinterpret_cast<uint4*>(dst + off) = q;
}

// ---------------------------------------------------------------------------
// bf16 GEMM: HMMA m16n8k16 f32-accum, cp.async.bulk feed of pre-swizzled
// contiguous tiles. CTA 128x128, BK=64, 3 stages, 4 compute warps
// (warp tile 64x64) + 1 producer thread; 2 CTAs/SM.
// ---------------------------------------------------------------------------
__device__ __forceinline__ void ldsm4(uint32_t addr, uint32_t& r0, uint32_t& r1,
                                      uint32_t& r2, uint32_t& r3) {
    asm volatile("ldmatrix.sync.aligned.m8n8.x4.shared.b16 {%0,%1,%2,%3}, [%4];\n"
                 : "=r"(r0), "=r"(r1), "=r"(r2), "=r"(r3)
                 : "r"(addr));
}
__device__ __forceinline__ void hmma(float* c, const uint32_t* a, const uint32_t* b) {
    asm volatile(
        "mma.sync.aligned.m16n8k16.row.col.f32.bf16.bf16.f32 "
        "{%0,%1,%2,%3}, {%4,%5,%6,%7}, {%8,%9}, {%0,%1,%2,%3};\n"
        : "+f"(c[0]), "+f"(c[1]), "+f"(c[2]), "+f"(c[3])
        : "r"(a[0]), "r"(a[1]), "r"(a[2]), "r"(a[3]), "r"(b[0]), "r"(b[1]));
}
__device__ __forceinline__ void bar_init(uint32_t bar, uint32_t cnt) {
    asm volatile("mbarrier.init.shared.b64 [%0], %1;" ::"r"(bar), "r"(cnt) : "memory");
}
__device__ __forceinline__ void bar_arrive(uint32_t bar) {
    asm volatile("mbarrier.arrive.shared.b64 _, [%0];" ::"r"(bar) : "memory");
}
__device__ __forceinline__ void bar_expect_tx(uint32_t bar, uint32_t bytes) {
    asm volatile("mbarrier.arrive.expect_tx.shared.b64 _, [%0], %1;"
                 ::"r"(bar), "r"(bytes) : "memory");
}
__device__ __forceinline__ void bar_wait(uint32_t bar, uint32_t parity) {
    asm volatile(
        "{\n\t.reg .pred P;\n\t"
        "BW_%=:\n\t"
        "mbarrier.try_wait.parity.acquire.cta.shared::cta.b64 P, [%0], %1, 0x989680;\n\t"
        "@P bra.uni BD_%=;\n\t"
        "bra.uni BW_%=;\n\t"
        "BD_%=:\n\t}"
        ::"r"(bar), "r"(parity) : "memory");
}
__device__ __forceinline__ void bulk_cp(uint32_t dst, const void* src,
                                        uint32_t bytes, uint32_t bar) {
    asm volatile(
        "cp.async.bulk.shared::cluster.global.mbarrier::complete_tx::bytes "
        "[%0], [%1], %2, [%3];"
        ::"r"(dst), "l"(src), "r"(bytes), "r"(bar) : "memory");
}
__device__ __forceinline__ void stcs2(float* p, float2 v) {
    asm volatile("st.global.cs.v2.f32 [%0], {%1, %2};" ::"l"(p), "f"(v.x), "f"(v.y)
                 : "memory");
}

__global__ void __launch_bounds__(160, 2)
hx_gemm(const float* __restrict__ bias, float* __restrict__ out) {
    extern __shared__ signed char smem[];
    __shared__ __align__(8) uint64_t s_bars[2 * NS];  // full[3], empty[3]

    const uint32_t sbase = (uint32_t)__cvta_generic_to_shared(smem);
    const uint32_t bar0 = (uint32_t)__cvta_generic_to_shared(&s_bars[0]);

    const int t = threadIdx.x;
    const int lane = t & 31;
    const int wid = t >> 5;
    const int m0 = blockIdx.y * BM;
    const int n0 = blockIdx.x * BN;

    if (t == 0) {
#pragma unroll
        for (int s = 0; s < NS; ++s) {
            bar_init(bar0 + 8 * s, 1);          // full[s]: producer expect_tx
            bar_init(bar0 + 8 * (NS + s), 4);   // empty[s]: 4 warp-leader arrivals
        }
    }
    __syncthreads();

    // ---------------- producer: thread 128 -----------------------------------
    if (t == 128) {
        const char* gA = reinterpret_cast<const char*>(g_qxb) +
                         (size_t)blockIdx.y * 64 * A_STAGE;
        const char* gB = reinterpret_cast<const char*>(g_qwb) +
                         (size_t)blockIdx.x * 64 * B_STAGE;
        int s = 0, ph = 1;
        for (int i = 0; i < NIT; ++i) {
            bar_wait(bar0 + 8 * (NS + s), (uint32_t)ph);  // empty[s]
            const uint32_t fb = bar0 + 8 * s;
            bar_expect_tx(fb, STAGE_BYTES_TX);
            const uint32_t ab = sbase + s * A_STAGE;
            const uint32_t bb = sbase + B_OFF + s * B_STAGE;
            const char* sa = gA + (size_t)i * A_STAGE;
            const char* sb = gB + (size_t)i * B_STAGE;
            bulk_cp(ab, sa, 8192, fb);
            bulk_cp(ab + 8192, sa + 8192, 8192, fb);
            bulk_cp(bb, sb, 8192, fb);
            bulk_cp(bb + 8192, sb + 8192, 8192, fb);
            if (++s == NS) { s = 0; ph ^= 1; }
        }
    }

    // ---------------- consumers: warps 0..3, warp tile 64x64 -----------------
    if (wid < 4) {
        const int wm = wid >> 1;  // 0..1
        const int wn = wid & 1;   // 0..1

        // Prefetch bias for this warp's 8 nf columns (column depends only on nf).
        float2 bz[8];
#pragma unroll
        for (int nf = 0; nf < 8; ++nf) {
            const int cg = n0 + wn * 64 + nf * 8 + 2 * (lane & 3);
            bz[nf] = *reinterpret_cast<const float2*>(bias + cg);
        }

        float acc[4][8][4];
#pragma unroll
        for (int a = 0; a < 4; ++a)
#pragma unroll
            for (int b = 0; b < 8; ++b)
#pragma unroll
                for (int r = 0; r < 4; ++r) acc[a][b][r] = 0.0f;

        int s = 0, ph = 0;
        for (int i = 0; i < NIT; ++i) {
            bar_wait(bar0 + 8 * s, (uint32_t)ph);  // full[s]
            const uint32_t abase = sbase + s * A_STAGE;
            const uint32_t bbase = sbase + B_OFF + s * B_STAGE;
#pragma unroll
            for (int ks = 0; ks < 4; ++ks) {  // 4 x k16 per BK=64
                uint32_t a[4][4];
#pragma unroll
                for (int mf = 0; mf < 4; ++mf) {
                    const int row =
                        wm * 64 + mf * 16 + (lane & 7) + ((lane >> 3) & 1) * 8;
                    const int kc = ks * 2 + (lane >> 4);  // 16B chunk
                    const uint32_t addr =
                        abase + row * 128 + ((kc ^ (row & 7)) << 4);
                    ldsm4(addr, a[mf][0], a[mf][1], a[mf][2], a[mf][3]);
                }
                uint32_t b[8][2];
#pragma unroll
                for (int p = 0; p < 4; ++p) {
                    const int nr = wn * 64 + (p * 2 + (lane >> 4)) * 8 + (lane & 7);
                    const int kc = ks * 2 + ((lane >> 3) & 1);
                    const uint32_t addr =
                        bbase + nr * 128 + ((kc ^ (nr & 7)) << 4);
                    ldsm4(addr, b[2 * p][0], b[2 * p][1], b[2 * p + 1][0],
                          b[2 * p + 1][1]);
                }
#pragma unroll
                for (int mf = 0; mf < 4; ++mf)
#pragma unroll
                    for (int nf = 0; nf < 8; ++nf) hmma(acc[mf][nf], a[mf], b[nf]);
            }
            __syncwarp();
            if (lane == 0) bar_arrive(bar0 + 8 * (NS + s));  // empty[s]
            if (++s == NS) { s = 0; ph ^= 1; }
        }

        // ---- epilogue: out = acc * invd + bias (acc is integer-valued) ----
        const float sx = 127.0f / __uint_as_float(g_amax[0]);
        const float sw = 127.0f / __uint_as_float(g_amax[1]);
        const float invd = 1.0f / (sx * sw);

#pragma unroll
        for (int mf = 0; mf < 4; ++mf) {
            const int r0 = m0 + wm * 64 + mf * 16 + (lane >> 2);
#pragma unroll
            for (int nf = 0; nf < 8; ++nf) {
                const int cg = n0 + wn * 64 + nf * 8 + 2 * (lane & 3);
                float2 o0, o1;
                o0.x = acc[mf][nf][0] * invd + bz[nf].x;
                o0.y = acc[mf][nf][1] * invd + bz[nf].y;
                o1.x = acc[mf][nf][2] * invd + bz[nf].x;
                o1.y = acc[mf][nf][3] * invd + bz[nf].y;
                stcs2(out + (size_t)r0 * N_DIM + cg, o0);
                stcs2(out + (size_t)(r0 + 8) * N_DIM + cg, o1);
            }
        }
    }
}

// ---------------------------------------------------------------------------
extern "C" void kernel_launch(void* const* d_in, const int* in_sizes, int n_in,
                              void* d_out, int out_size) {
    const float* x = (const float*)d_in[0];
    const float* w = (const float*)d_in[1];
    const float* bias = (const float*)d_in[2];
    float* out = (float*)d_out;
    (void)in_sizes; (void)n_in; (void)out_size;

    cudaFuncSetAttribute(hx_gemm, cudaFuncAttributeMaxDynamicSharedMemorySize,
                         SMEM_TC);

    hx_init<<<1, 1>>>();
    hx_amax2<<<3072, 256>>>((const float4*)x, (const float4*)w);
    hx_quant2<<<24576, 256>>>((const float4*)x, (const float4*)w);

    dim3 grid(N_DIM / BN, M_DIM / BM);  // (32, 64)
    hx_gemm<<<grid, 160, SMEM_TC>>>(bias, out);
}